// round 2
// baseline (speedup 1.0000x reference)
#include <cuda_runtime.h>
#include <cuda_bf16.h>

// Problem constants
#define BB 4
#define LL 4096
#define DD 256
#define AA 64
#define BM 64
#define BN 64

// Scratch for projected Q,K,V: [B, L, A] each, stored as float4 (A/4 = 16 per row)
__device__ float4 g_Q[BB * LL * (AA / 4)];
__device__ float4 g_K[BB * LL * (AA / 4)];
__device__ float4 g_V[BB * LL * (AA / 4)];

// ---------------------------------------------------------------------------
// QKV projection: rows = B*L = 16384, x[row][256] @ W[256][64] for 3 matrices.
// Block: 192 threads = 3 matrices x 64 cols; 32 rows per block.
// ---------------------------------------------------------------------------
__global__ __launch_bounds__(192) void qkv_kernel(
    const float* __restrict__ x,
    const float* __restrict__ Wq,
    const float* __restrict__ Wk,
    const float* __restrict__ Wv)
{
    __shared__ float4 xs4[32 * 64];  // 32 rows x 256 floats = 32KB

    const int row0 = blockIdx.x * 32;
    const int tid = threadIdx.x;

    // Load x tile (linear copy, coalesced)
    const float4* xg = reinterpret_cast<const float4*>(x) + (size_t)row0 * 64;
    for (int i = tid; i < 32 * 64; i += 192) xs4[i] = xg[i];
    __syncthreads();

    const int c = tid & 63;
    const int m = tid >> 6;  // 0=Q, 1=K, 2=V
    const float* W = (m == 0) ? Wq : ((m == 1) ? Wk : Wv);
    float* outf = (float*)((m == 0) ? g_Q : ((m == 1) ? g_K : g_V));

    float acc[32];
#pragma unroll
    for (int r = 0; r < 32; r++) acc[r] = 0.f;

    for (int d4 = 0; d4 < 64; d4++) {
        const int d = d4 * 4;
        const float w0 = W[(d + 0) * AA + c];
        const float w1 = W[(d + 1) * AA + c];
        const float w2 = W[(d + 2) * AA + c];
        const float w3 = W[(d + 3) * AA + c];
#pragma unroll
        for (int r = 0; r < 32; r++) {
            const float4 xv = xs4[r * 64 + d4];
            acc[r] += xv.x * w0 + xv.y * w1 + xv.z * w2 + xv.w * w3;
        }
    }

#pragma unroll
    for (int r = 0; r < 32; r++)
        outf[(size_t)(row0 + r) * AA + c] = acc[r];
}

// ---------------------------------------------------------------------------
// Causal flash attention, fp32 SIMT.
// Grid: B * (L/BM) = 256 blocks, 64 threads each (1 thread = 1 query row).
// Heaviest query tiles launched first (reverse qt order).
// smem: K tile 16KB + V tile 16KB + S tile 16KB = 48KB exactly.
// ---------------------------------------------------------------------------
__global__ __launch_bounds__(64) void attn_kernel(float* __restrict__ out)
{
    __shared__ float4 Ks[BN * 16];     // 64 rows x 16 float4
    __shared__ float4 Vs[BN * 16];
    __shared__ float  Ssm[BN * BM];    // [j][r] layout: lane-consecutive in r

    const int bid = blockIdx.x;
    const int nQT = LL / BM;                 // 64
    const int qt = nQT - 1 - (bid >> 2);     // heavy tiles first
    const int b = bid & 3;
    const int r = threadIdx.x;
    const int q0 = qt * BM;
    const int qi = q0 + r;

    // q row into registers
    float4 q4[16];
    const float4* Qg = g_Q + ((size_t)b * LL + qi) * 16;
#pragma unroll
    for (int i = 0; i < 16; i++) q4[i] = Qg[i];

    float o[AA];
#pragma unroll
    for (int d = 0; d < AA; d++) o[d] = 0.f;
    float mrow = -1e30f;
    float lrow = 0.f;

    const float4* Kb = g_K + (size_t)b * LL * 16;
    const float4* Vb = g_V + (size_t)b * LL * 16;

    for (int kt = 0; kt <= qt; kt++) {
        const int j0 = kt * BN;
        const float4* Kg = Kb + (size_t)j0 * 16;
        const float4* Vg = Vb + (size_t)j0 * 16;
#pragma unroll
        for (int i = 0; i < 16; i++) {
            Ks[i * 64 + r] = Kg[i * 64 + r];
            Vs[i * 64 + r] = Vg[i * 64 + r];
        }
        __syncthreads();

        const bool diag = (kt == qt);

        // S = q . k_j for all 64 keys; 4 partial sums for FFMA ILP
        for (int j = 0; j < BN; j++) {
            float s0 = 0.f, s1 = 0.f, s2 = 0.f, s3 = 0.f;
#pragma unroll
            for (int i = 0; i < 16; i += 4) {
                const float4 k0 = Ks[j * 16 + i + 0];
                s0 += q4[i + 0].x * k0.x + q4[i + 0].y * k0.y + q4[i + 0].z * k0.z + q4[i + 0].w * k0.w;
                const float4 k1 = Ks[j * 16 + i + 1];
                s1 += q4[i + 1].x * k1.x + q4[i + 1].y * k1.y + q4[i + 1].z * k1.z + q4[i + 1].w * k1.w;
                const float4 k2 = Ks[j * 16 + i + 2];
                s2 += q4[i + 2].x * k2.x + q4[i + 2].y * k2.y + q4[i + 2].z * k2.z + q4[i + 2].w * k2.w;
                const float4 k3 = Ks[j * 16 + i + 3];
                s3 += q4[i + 3].x * k3.x + q4[i + 3].y * k3.y + q4[i + 3].z * k3.z + q4[i + 3].w * k3.w;
            }
            float s = (s0 + s1) + (s2 + s3);
            if (diag && j > r) s = -1e30f;   // causal mask (only diagonal tile)
            Ssm[j * 64 + r] = s;
        }

        // Online softmax update (row-local; no barriers needed for Ssm)
        float mt = -1e30f;
        for (int j = 0; j < BN; j++) mt = fmaxf(mt, Ssm[j * 64 + r]);
        const float mnew = fmaxf(mrow, mt);
        const float scale = __expf(mrow - mnew);
        mrow = mnew;
        lrow *= scale;
#pragma unroll
        for (int d = 0; d < AA; d++) o[d] *= scale;

        for (int j = 0; j < BN; j++) {
            const float p = __expf(Ssm[j * 64 + r] - mnew);
            lrow += p;
            Ssm[j * 64 + r] = p;
        }

        // O += P @ V
        for (int j = 0; j < BN; j++) {
            const float p = Ssm[j * 64 + r];
#pragma unroll
            for (int i = 0; i < 16; i++) {
                const float4 v = Vs[j * 16 + i];
                o[i * 4 + 0] += p * v.x;
                o[i * 4 + 1] += p * v.y;
                o[i * 4 + 2] += p * v.z;
                o[i * 4 + 3] += p * v.w;
            }
        }
        __syncthreads();  // protect K/V tiles before next load
    }

    const float inv = 1.f / lrow;
    float4* og = reinterpret_cast<float4*>(out) + ((size_t)b * LL + qi) * 16;
#pragma unroll
    for (int i = 0; i < 16; i++) {
        float4 v;
        v.x = o[i * 4 + 0] * inv;
        v.y = o[i * 4 + 1] * inv;
        v.z = o[i * 4 + 2] * inv;
        v.w = o[i * 4 + 3] * inv;
        og[i] = v;
    }
}

// ---------------------------------------------------------------------------
extern "C" void kernel_launch(void* const* d_in, const int* in_sizes, int n_in,
                              void* d_out, int out_size)
{
    const float* x  = (const float*)d_in[0];
    const float* Wq = (const float*)d_in[1];
    const float* Wk = (const float*)d_in[2];
    const float* Wv = (const float*)d_in[3];
    float* out = (float*)d_out;

    // QKV projection: 16384 rows / 32 per block
    qkv_kernel<<<(BB * LL) / 32, 192>>>(x, Wq, Wk, Wv);

    // Attention: B * (L/BM) blocks
    attn_kernel<<<BB * (LL / BM), BM>>>(out);
}

// round 3
// speedup vs baseline: 1.6824x; 1.6824x over previous
#include <cuda_runtime.h>
#include <cuda_bf16.h>

// Problem constants
#define BB 4
#define LL 4096
#define DD 256
#define AA 64
#define BM 64
#define BN 64

// Scratch for projected Q,K,V: [B, L, A] each, stored as float4 (A/4 = 16 per row)
__device__ float4 g_Q[BB * LL * (AA / 4)];
__device__ float4 g_K[BB * LL * (AA / 4)];
__device__ float4 g_V[BB * LL * (AA / 4)];

// ---------------------------------------------------------------------------
// QKV projection: rows = B*L = 16384, x[row][256] @ W[256][64] for 3 matrices.
// Block: 192 threads = 3 matrices x 64 cols; 32 rows per block.
// ---------------------------------------------------------------------------
__global__ __launch_bounds__(192) void qkv_kernel(
    const float* __restrict__ x,
    const float* __restrict__ Wq,
    const float* __restrict__ Wk,
    const float* __restrict__ Wv)
{
    __shared__ float4 xs4[32 * 64];  // 32 rows x 256 floats = 32KB

    const int row0 = blockIdx.x * 32;
    const int tid = threadIdx.x;

    const float4* xg = reinterpret_cast<const float4*>(x) + (size_t)row0 * 64;
    for (int i = tid; i < 32 * 64; i += 192) xs4[i] = xg[i];
    __syncthreads();

    const int c = tid & 63;
    const int m = tid >> 6;  // 0=Q, 1=K, 2=V
    const float* W = (m == 0) ? Wq : ((m == 1) ? Wk : Wv);
    float* outf = (float*)((m == 0) ? g_Q : ((m == 1) ? g_K : g_V));

    float acc[32];
#pragma unroll
    for (int r = 0; r < 32; r++) acc[r] = 0.f;

    for (int d4 = 0; d4 < 64; d4++) {
        const int d = d4 * 4;
        const float w0 = W[(d + 0) * AA + c];
        const float w1 = W[(d + 1) * AA + c];
        const float w2 = W[(d + 2) * AA + c];
        const float w3 = W[(d + 3) * AA + c];
#pragma unroll
        for (int r = 0; r < 32; r++) {
            const float4 xv = xs4[r * 64 + d4];
            acc[r] += xv.x * w0 + xv.y * w1 + xv.z * w2 + xv.w * w3;
        }
    }

#pragma unroll
    for (int r = 0; r < 32; r++)
        outf[(size_t)(row0 + r) * AA + c] = acc[r];
}

// ---------------------------------------------------------------------------
// Causal flash attention, fp32, register-tiled.
// Grid: B * (L/BM) = 256 blocks, 128 threads (4 warps).
// Thread (tx 0..15, ty 0..7) owns S/O tile: rows ty*8..+7, cols tx*4..+3.
// Q,K transposed [d][row] in smem; V natural [j][d]; P in smem [r][j] stride 68.
// ---------------------------------------------------------------------------
__global__ __launch_bounds__(128) void attn_kernel(float* __restrict__ out)
{
    __shared__ float Qs[AA * BM];        // [d][r]  16KB
    __shared__ float Ks[AA * BN];        // [d][j]  16KB
    __shared__ float Vs[BN * AA];        // [j][d]  16KB
    __shared__ float Ps[BM * 68];        // [r][j]  stride 68, 17KB

    const int bid = blockIdx.x;
    const int u = bid >> 2;              // 0..63 query-tile slot
    const int qt = (u & 1) ? (u >> 1) : (63 - (u >> 1));  // zigzag: heavy+light interleaved
    const int b = bid & 3;
    const int tid = threadIdx.x;
    const int tx = tid & 15;
    const int ty = tid >> 4;
    const int q0 = qt * BM;

    // Load Q tile transposed into smem: thread -> (row = tid/2, half = tid&1)
    {
        const float4* Qg = g_Q + ((size_t)b * LL + q0) * 16;
        const int r = tid >> 1;
        const int h = (tid & 1) * 8;
#pragma unroll
        for (int i = 0; i < 8; i++) {
            const float4 v = Qg[r * 16 + h + i];
            const int d = (h + i) * 4;
            Qs[(d + 0) * 64 + r] = v.x;
            Qs[(d + 1) * 64 + r] = v.y;
            Qs[(d + 2) * 64 + r] = v.z;
            Qs[(d + 3) * 64 + r] = v.w;
        }
    }

    float o[32];
#pragma unroll
    for (int i = 0; i < 32; i++) o[i] = 0.f;
    float m_r[8], l_r[8];
#pragma unroll
    for (int i = 0; i < 8; i++) { m_r[i] = -1e30f; l_r[i] = 0.f; }

    const float4* Kb = g_K + (size_t)b * LL * 16;
    const float4* Vb = g_V + (size_t)b * LL * 16;

    for (int kt = 0; kt <= qt; kt++) {
        __syncthreads();   // previous tile's K/V/P reads done; Qs writes visible (1st iter)

        // Load K transposed, V direct
        {
            const float4* Kg = Kb + (size_t)kt * BN * 16;
            const int j = tid >> 1;
            const int h = (tid & 1) * 8;
#pragma unroll
            for (int i = 0; i < 8; i++) {
                const float4 v = Kg[j * 16 + h + i];
                const int d = (h + i) * 4;
                Ks[(d + 0) * 64 + j] = v.x;
                Ks[(d + 1) * 64 + j] = v.y;
                Ks[(d + 2) * 64 + j] = v.z;
                Ks[(d + 3) * 64 + j] = v.w;
            }
            const float4* Vg = Vb + (size_t)kt * BN * 16;
            float4* Vs4 = (float4*)Vs;
#pragma unroll
            for (int i = 0; i < 8; i++)
                Vs4[i * 128 + tid] = Vg[i * 128 + tid];
        }
        __syncthreads();

        // ---- GEMM1: S[8][4] = Q_rows . K_cols ----
        float S[8][4];
#pragma unroll
        for (int rr = 0; rr < 8; rr++)
#pragma unroll
            for (int cc = 0; cc < 4; cc++) S[rr][cc] = 0.f;

#pragma unroll 4
        for (int d = 0; d < AA; d++) {
            const float4 k4 = *(const float4*)&Ks[d * 64 + tx * 4];
            const float4 qa = *(const float4*)&Qs[d * 64 + ty * 8];
            const float4 qb = *(const float4*)&Qs[d * 64 + ty * 8 + 4];
            const float qv[8] = {qa.x, qa.y, qa.z, qa.w, qb.x, qb.y, qb.z, qb.w};
            const float kv[4] = {k4.x, k4.y, k4.z, k4.w};
#pragma unroll
            for (int rr = 0; rr < 8; rr++)
#pragma unroll
                for (int cc = 0; cc < 4; cc++)
                    S[rr][cc] += qv[rr] * kv[cc];
        }

        // Causal mask (diagonal tile only)
        if (kt == qt) {
#pragma unroll
            for (int rr = 0; rr < 8; rr++)
#pragma unroll
                for (int cc = 0; cc < 4; cc++)
                    if (tx * 4 + cc > ty * 8 + rr) S[rr][cc] = -1e30f;
        }

        // ---- Online softmax (row reductions over 16 lanes = half-warp) ----
#pragma unroll
        for (int rr = 0; rr < 8; rr++) {
            float mt = fmaxf(fmaxf(S[rr][0], S[rr][1]), fmaxf(S[rr][2], S[rr][3]));
            mt = fmaxf(mt, __shfl_xor_sync(0xffffffffu, mt, 1));
            mt = fmaxf(mt, __shfl_xor_sync(0xffffffffu, mt, 2));
            mt = fmaxf(mt, __shfl_xor_sync(0xffffffffu, mt, 4));
            mt = fmaxf(mt, __shfl_xor_sync(0xffffffffu, mt, 8));
            const float mnew = fmaxf(m_r[rr], mt);
            const float sc = __expf(m_r[rr] - mnew);
            m_r[rr] = mnew;
            float ps = 0.f;
#pragma unroll
            for (int cc = 0; cc < 4; cc++) {
                S[rr][cc] = __expf(S[rr][cc] - mnew);
                ps += S[rr][cc];
            }
            ps += __shfl_xor_sync(0xffffffffu, ps, 1);
            ps += __shfl_xor_sync(0xffffffffu, ps, 2);
            ps += __shfl_xor_sync(0xffffffffu, ps, 4);
            ps += __shfl_xor_sync(0xffffffffu, ps, 8);
            l_r[rr] = l_r[rr] * sc + ps;
#pragma unroll
            for (int dd = 0; dd < 4; dd++) o[rr * 4 + dd] *= sc;
            const float4 p4 = make_float4(S[rr][0], S[rr][1], S[rr][2], S[rr][3]);
            *(float4*)&Ps[(ty * 8 + rr) * 68 + tx * 4] = p4;
        }
        __syncwarp();   // P rows are produced & consumed within the same half-warp

        // ---- GEMM2: O[8][4] += P_rows . V ----
#pragma unroll 2
        for (int j = 0; j < BN; j++) {
            const float4 v4 = *(const float4*)&Vs[j * 64 + tx * 4];
            const float vv[4] = {v4.x, v4.y, v4.z, v4.w};
#pragma unroll
            for (int rr = 0; rr < 8; rr++) {
                const float p = Ps[(ty * 8 + rr) * 68 + j];
#pragma unroll
                for (int dd = 0; dd < 4; dd++)
                    o[rr * 4 + dd] += p * vv[dd];
            }
        }
    }

    // Epilogue: normalize and store
    float4* og = reinterpret_cast<float4*>(out) + ((size_t)b * LL + q0) * 16;
#pragma unroll
    for (int rr = 0; rr < 8; rr++) {
        const float inv = 1.f / l_r[rr];
        float4 v;
        v.x = o[rr * 4 + 0] * inv;
        v.y = o[rr * 4 + 1] * inv;
        v.z = o[rr * 4 + 2] * inv;
        v.w = o[rr * 4 + 3] * inv;
        og[(ty * 8 + rr) * 16 + tx] = v;
    }
}

// ---------------------------------------------------------------------------
extern "C" void kernel_launch(void* const* d_in, const int* in_sizes, int n_in,
                              void* d_out, int out_size)
{
    const float* x  = (const float*)d_in[0];
    const float* Wq = (const float*)d_in[1];
    const float* Wk = (const float*)d_in[2];
    const float* Wv = (const float*)d_in[3];
    float* out = (float*)d_out;

    qkv_kernel<<<(BB * LL) / 32, 192>>>(x, Wq, Wk, Wv);
    attn_kernel<<<BB * (LL / BM), 128>>>(out);
}